// round 1
// baseline (speedup 1.0000x reference)
#include <cuda_runtime.h>
#include <cuda_bf16.h>
#include <math.h>

// Problem constants
#define BATCH 8
#define NSTMT 80
#define NNODE 81
#define HID   256
#define H4    1024
#define NSTEP 8
#define VOCAB 30000
#define CHAINS (NNODE*BATCH)   // 648

// ---------------- device scratch (allocation-free) ----------------
static __device__ float d_SKIP[BATCH*NNODE*NNODE*HID];   // [b][n=start][m=pos][h]
static __device__ float d_KEYS[BATCH*NNODE*NNODE*HID];
static __device__ float d_STMT[BATCH*NSTMT*HID];
static __device__ float d_XG0 [BATCH*NSTMT*H4];          // stmt@skWx0 + skb0
static __device__ float d_SC0[CHAINS*HID];
static __device__ float d_SH0[CHAINS*HID];
static __device__ float d_SC1[CHAINS*HID];
static __device__ float d_SH1[CHAINS*HID];
static __device__ float d_XH1[CHAINS*512];               // [h0new, h1prev]
static __device__ float d_G0 [CHAINS*H4];
static __device__ float d_G1 [CHAINS*H4];
static __device__ float d_W1CAT[512*H4];                 // [skWx1; skWh1]
static __device__ float d_EXW0 [512*H4];                 // [exWx0; exWh0]
static __device__ float d_EXW1 [512*H4];                 // [exWx1; exWh1]
static __device__ float d_HC [CHAINS*H4];                // exec state: c0,h0,c1,h1
static __device__ float d_Q  [CHAINS*HID];
static __device__ float d_T  [BATCH*NNODE*NNODE];
static __device__ float d_P  [CHAINS];
static __device__ float d_XHE[CHAINS*512];               // [x_in, h0prop]
static __device__ float d_XH2[CHAINS*512];               // [h0new, h1prop]
static __device__ float d_CPR[CHAINS*512];               // [c0prop, c1prop]
static __device__ float d_HP1[CHAINS*HID];               // h1prop (also stmt tmp)
static __device__ float d_GE [CHAINS*H4];

// ---------------- helpers ----------------
__device__ __forceinline__ float sigf(float x){ return 1.f/(1.f+__expf(-x)); }
__device__ __forceinline__ float ftanh(float x){
    // tanh(x) = 1 - 2/(exp(2x)+1); __expf handles +-inf limits correctly
    return 1.f - 2.f/(__expf(2.f*x)+1.f);
}

__device__ __forceinline__ float block_sum(float v, float* sh) {
    int lane = threadIdx.x & 31, w = threadIdx.x >> 5;
    #pragma unroll
    for (int o = 16; o; o >>= 1) v += __shfl_xor_sync(0xffffffffu, v, o);
    __syncthreads();
    if (lane == 0) sh[w] = v;
    __syncthreads();
    return sh[0]+sh[1]+sh[2]+sh[3]+sh[4]+sh[5]+sh[6]+sh[7];
}

// ---------------- init / weight prep ----------------
__global__ void init_kernel() {
    int stride = gridDim.x * blockDim.x;
    int gid = blockIdx.x * blockDim.x + threadIdx.x;
    for (int i = gid; i < BATCH*NNODE*NNODE*HID; i += stride) d_SKIP[i] = 0.f;
    for (int i = gid; i < CHAINS*HID; i += stride) {
        d_SC0[i]=0.f; d_SH0[i]=0.f; d_SC1[i]=0.f; d_SH1[i]=0.f;
    }
    for (int i = gid; i < CHAINS*H4; i += stride) d_HC[i] = 0.f;
    for (int i = gid; i < CHAINS; i += stride) d_P[i] = (i % NNODE == 0) ? 1.f : 0.f;
}

__global__ void build_cats(const float* __restrict__ skWx, const float* __restrict__ skWh,
                           const float* __restrict__ exWx, const float* __restrict__ exWh) {
    int i = blockIdx.x*256 + threadIdx.x;
    if (i >= 512*H4) return;
    int k = i >> 10, n = i & 1023;
    const int L1 = 256*H4; // layer-1 offset inside [L,H,4H]
    d_W1CAT[i] = (k < 256) ? skWx[L1 + k*H4 + n] : skWh[L1 + (k-256)*H4 + n];
    d_EXW0[i]  = (k < 256) ? exWx[k*H4 + n]      : exWh[(k-256)*H4 + n];
    d_EXW1[i]  = (k < 256) ? exWx[L1 + k*H4 + n] : exWh[L1 + (k-256)*H4 + n];
}

// ---------------- generic fp32 GEMM: C = A[MxK] @ B[KxN] (+bias) ----------------
#define BM 64
#define BN 64
#define BK 16
__global__ void __launch_bounds__(256) gemm_bias(const float* __restrict__ A,
                                                 const float* __restrict__ B,
                                                 const float* __restrict__ bias,
                                                 float* __restrict__ C,
                                                 int M, int N, int K) {
    __shared__ float As[BK][BM];
    __shared__ float Bs[BK][BN];
    int tid = threadIdx.x;
    int tx = tid & 15, ty = tid >> 4;
    int row0 = blockIdx.y * BM;
    int col0 = blockIdx.x * BN;
    float acc[4][4] = {};
    for (int k0 = 0; k0 < K; k0 += BK) {
        #pragma unroll
        for (int i = tid; i < BM*BK; i += 256) {
            int m = i / BK, kk = i % BK;
            int gm = row0 + m;
            As[kk][m] = (gm < M) ? A[gm*K + k0 + kk] : 0.f;
        }
        #pragma unroll
        for (int i = tid; i < BK*BN; i += 256) {
            int kk = i / BN, n = i % BN;
            int gn = col0 + n;
            Bs[kk][n] = (gn < N) ? B[(k0+kk)*N + gn] : 0.f;
        }
        __syncthreads();
        #pragma unroll
        for (int kk = 0; kk < BK; kk++) {
            float a[4], b[4];
            #pragma unroll
            for (int i = 0; i < 4; i++) a[i] = As[kk][ty*4+i];
            #pragma unroll
            for (int j = 0; j < 4; j++) b[j] = Bs[kk][tx*4+j];
            #pragma unroll
            for (int i = 0; i < 4; i++)
                #pragma unroll
                for (int j = 0; j < 4; j++)
                    acc[i][j] += a[i]*b[j];
        }
        __syncthreads();
    }
    #pragma unroll
    for (int i = 0; i < 4; i++) {
        int gm = row0 + ty*4 + i;
        if (gm >= M) continue;
        #pragma unroll
        for (int j = 0; j < 4; j++) {
            int gn = col0 + tx*4 + j;
            if (gn >= N) continue;
            float v = acc[i][j];
            if (bias) v += bias[gn];
            C[gm*N + gn] = v;
        }
    }
}

// ---------------- statement embedder elementwise (zero carry) ----------------
__global__ void __launch_bounds__(256) lstm_elt_first(const float* __restrict__ G,
                                                      float* __restrict__ Hout) {
    int r = blockIdx.x, j = threadIdx.x;
    const float* g = G + r*H4;
    float c = sigf(g[j]) * ftanh(g[512+j]);       // sig(i)*tanh(g)   (c_prev = 0)
    Hout[r*HID + j] = sigf(g[768+j]) * ftanh(c);  // sig(o)*tanh(c)
}

// ---------------- skip-encoder per-step elementwise ----------------
__global__ void __launch_bounds__(256) skip_elt0(int idx) {
    int c = blockIdx.x, j = threadIdx.x;
    int b = c & 7;
    const float* g0 = d_G0 + c*H4;
    const float* xg = d_XG0 + (b*NSTMT + idx)*H4;
    float gi = g0[j]      + xg[j];
    float gf = g0[256+j]  + xg[256+j];
    float gg = g0[512+j]  + xg[512+j];
    float go = g0[768+j]  + xg[768+j];
    float cv = sigf(gf)*d_SC0[c*HID+j] + sigf(gi)*ftanh(gg);
    float hv = sigf(go)*ftanh(cv);
    d_SC0[c*HID+j] = cv;           // raw (LN applied later)
    d_SH0[c*HID+j] = hv;           // raw
    d_XH1[c*512 + j]       = hv;           // layer-1 input x
    d_XH1[c*512 + 256 + j] = d_SH1[c*HID+j]; // layer-1 recurrent h (prev, LN'd)
}

__global__ void __launch_bounds__(256) skip_elt_ln(int idx,
                                                   const float* __restrict__ lns,
                                                   const float* __restrict__ lnb) {
    __shared__ float sh[8];
    int c = blockIdx.x, j = threadIdx.x;
    int s = c >> 3, b = c & 7;
    const float* g1 = d_G1 + c*H4;
    float c1 = sigf(g1[256+j])*d_SC1[c*HID+j] + sigf(g1[j])*ftanh(g1[512+j]);
    float h1 = sigf(g1[768+j])*ftanh(c1);
    float v0 = d_SC0[c*HID+j], v1 = d_SH0[c*HID+j];
    float mu = block_sum(v0+v1+c1+h1, sh) * (1.f/1024.f);
    float e0 = v0-mu, e1 = v1-mu, e2 = c1-mu, e3 = h1-mu;
    float var = block_sum(e0*e0+e1*e1+e2*e2+e3*e3, sh) * (1.f/1024.f);
    float rs = rsqrtf(var + 1e-6f);
    d_SC0[c*HID+j] = e0*rs*lns[j]      + lnb[j];
    d_SH0[c*HID+j] = e1*rs*lns[256+j]  + lnb[256+j];
    d_SC1[c*HID+j] = e2*rs*lns[512+j]  + lnb[512+j];
    d_SH1[c*HID+j] = e3*rs*lns[768+j]  + lnb[768+j];
    // out is PRE-LN top-layer h, prepended zero row -> position idx+1
    d_SKIP[((b*NNODE + s)*NNODE + (idx+1))*HID + j] = h1;
}

// ---------------- main-loop kernels ----------------
__global__ void __launch_bounds__(256) attn_kernel(const float* __restrict__ w1,
                                                   const float* __restrict__ b1, int step) {
    int bn = blockIdx.x;               // b*81 + n
    int n = bn % NNODE;
    __shared__ float qsh[HID], w1sh[HID], lg[NNODE];
    int tid = threadIdx.x;
    qsh[tid]  = d_Q[bn*HID + tid];
    w1sh[tid] = w1[tid];
    __syncthreads();
    int w = tid >> 5, lane = tid & 31;
    float b1v = b1[0];
    for (int m = w; m < NNODE; m += 8) {
        const float* kr = d_KEYS + (bn*NNODE + m)*HID;
        float acc = 0.f;
        #pragma unroll 4
        for (int h = lane; h < HID; h += 32)
            acc += ftanh(qsh[h] + kr[h]) * w1sh[h];
        #pragma unroll
        for (int o = 16; o; o >>= 1) acc += __shfl_xor_sync(0xffffffffu, acc, o);
        if (lane == 0) {
            bool allowed = (step == 0) ? (m == 1)
                        : ((step == NSTEP-1) ? (m == NNODE-1)
                                             : (m > n || m == NNODE-1));
            lg[m] = allowed ? (acc + b1v) : -1e9f;
        }
    }
    __syncthreads();
    if (w == 0) {
        float mx = -1e30f;
        for (int m = lane; m < NNODE; m += 32) mx = fmaxf(mx, lg[m]);
        #pragma unroll
        for (int o = 16; o; o >>= 1) mx = fmaxf(mx, __shfl_xor_sync(0xffffffffu, mx, o));
        float sum = 0.f;
        for (int m = lane; m < NNODE; m += 32) { float e = expf(lg[m]-mx); lg[m] = e; sum += e; }
        #pragma unroll
        for (int o = 16; o; o >>= 1) sum += __shfl_xor_sync(0xffffffffu, sum, o);
        float scale = d_P[bn] / sum;
        for (int m = lane; m < NNODE; m += 32) d_T[bn*NNODE + m] = lg[m]*scale;
    }
}

__global__ void newp_kernel() {
    int b = blockIdx.x, m = threadIdx.x;
    if (m < NNODE) {
        float s = 0.f;
        for (int n = 0; n < NNODE; n++) s += d_T[(b*NNODE+n)*NNODE + m];
        d_P[b*NNODE + m] = s;
    }
}

__global__ void __launch_bounds__(256) props_kernel() {
    int bm = blockIdx.x;
    int b = bm / NNODE, m = bm % NNODE;
    __shared__ float tsh[NNODE];
    int tid = threadIdx.x;
    if (tid < NNODE) tsh[tid] = d_T[(b*NNODE+tid)*NNODE + m];
    __syncthreads();
    float inv = 1.f / (d_P[bm] + 1e-7f);
    float ax=0.f, a0=0.f, a1=0.f, a2=0.f, a3=0.f;
    for (int n = 0; n < NNODE; n++) {
        float tv = tsh[n];
        if (tv == 0.f) continue;
        const float* sr = d_SKIP + ((b*NNODE+n)*NNODE + m)*HID;
        const float* hr = d_HC + (b*NNODE+n)*H4;
        ax += tv*sr[tid];
        a0 += tv*hr[tid];      a1 += tv*hr[256+tid];
        a2 += tv*hr[512+tid];  a3 += tv*hr[768+tid];
    }
    d_XHE[bm*512 + tid]       = ax*inv;  // x_in
    d_CPR[bm*512 + tid]       = a0*inv;  // c0 prop
    d_XHE[bm*512 + 256 + tid] = a1*inv;  // h0 prop (recurrent input L0)
    d_CPR[bm*512 + 256 + tid] = a2*inv;  // c1 prop
    d_HP1[bm*HID + tid]       = a3*inv;  // h1 prop (recurrent input L1)
}

__global__ void __launch_bounds__(256) exec_elt0() {
    int e = blockIdx.x, j = threadIdx.x;
    const float* g = d_GE + e*H4;
    float cv = sigf(g[256+j])*d_CPR[e*512+j] + sigf(g[j])*ftanh(g[512+j]);
    float hv = sigf(g[768+j])*ftanh(cv);
    d_HC[e*H4 + j]       = cv;
    d_HC[e*H4 + 256 + j] = hv;
    d_XH2[e*512 + j]       = hv;
    d_XH2[e*512 + 256 + j] = d_HP1[e*HID + j];
}

__global__ void __launch_bounds__(256) exec_elt1() {
    int e = blockIdx.x, j = threadIdx.x;
    const float* g = d_GE + e*H4;
    float cv = sigf(g[256+j])*d_CPR[e*512+256+j] + sigf(g[j])*ftanh(g[512+j]);
    float hv = sigf(g[768+j])*ftanh(cv);
    d_HC[e*H4 + 512 + j] = cv;
    d_HC[e*H4 + 768 + j] = hv;
}

// ---------------- output projection ----------------
__global__ void __launch_bounds__(256) out_kernel(const int* __restrict__ exit_idx,
                                                  const float* __restrict__ wo,
                                                  const float* __restrict__ bo,
                                                  float* __restrict__ out) {
    __shared__ float hex[BATCH][HID];
    int tid = threadIdx.x;
    for (int i = tid; i < BATCH*HID; i += 256) {
        int b = i >> 8, h = i & 255;
        hex[b][h] = d_HC[(b*NNODE + exit_idx[b])*H4 + 768 + h];
    }
    __syncthreads();
    int col = blockIdx.x*256 + tid;
    if (col >= VOCAB) return;
    float acc[BATCH];
    #pragma unroll
    for (int b = 0; b < BATCH; b++) acc[b] = 0.f;
    for (int h = 0; h < HID; h++) {
        float wv = wo[h*VOCAB + col];
        #pragma unroll
        for (int b = 0; b < BATCH; b++) acc[b] += hex[b][h]*wv;
    }
    float bv = bo[col];
    #pragma unroll
    for (int b = 0; b < BATCH; b++) out[b*VOCAB + col] = acc[b] + bv;
}

// ---------------- host ----------------
static inline void launch_gemm(const float* A, const float* B, const float* bias,
                               float* C, int M, int N, int K) {
    dim3 g((N + BN - 1)/BN, (M + BM - 1)/BM);
    gemm_bias<<<g, 256>>>(A, B, bias, C, M, N, K);
}

static inline float* sym(const void* s) {
    void* p = nullptr;
    cudaGetSymbolAddress(&p, s);
    return (float*)p;
}

extern "C" void kernel_launch(void* const* d_in, const int* in_sizes, int n_in,
                              void* d_out, int out_size) {
    const float* node_emb = (const float*)d_in[0];
    const int*   exit_idx = (const int*)  d_in[10];
    const float* st_Wx = (const float*)d_in[12];
    const float* st_b  = (const float*)d_in[14];
    const float* sk_Wx = (const float*)d_in[15];
    const float* sk_Wh = (const float*)d_in[16];
    const float* sk_b  = (const float*)d_in[17];
    const float* ln_s  = (const float*)d_in[18];
    const float* ln_b  = (const float*)d_in[19];
    const float* ex_Wx = (const float*)d_in[20];
    const float* ex_Wh = (const float*)d_in[21];
    const float* ex_b  = (const float*)d_in[22];
    const float* wk = (const float*)d_in[23];
    const float* bk = (const float*)d_in[24];
    const float* ws = (const float*)d_in[25];
    const float* bs = (const float*)d_in[26];
    const float* w1 = (const float*)d_in[27];
    const float* b1 = (const float*)d_in[28];
    const float* wo = (const float*)d_in[29];
    const float* bo = (const float*)d_in[30];
    float* out = (float*)d_out;

    float* pG0   = sym(d_G0);
    float* pG1   = sym(d_G1);
    float* pHP1  = sym(d_HP1);
    float* pSTMT = sym(d_STMT);
    float* pXG0  = sym(d_XG0);
    float* pSKIP = sym(d_SKIP);
    float* pKEYS = sym(d_KEYS);
    float* pSH0  = sym(d_SH0);
    float* pXH1  = sym(d_XH1);
    float* pHC   = sym(d_HC);
    float* pQ    = sym(d_Q);
    float* pXHE  = sym(d_XHE);
    float* pXH2  = sym(d_XH2);
    float* pGE   = sym(d_GE);
    float* pW1C  = sym(d_W1CAT);
    float* pEW0  = sym(d_EXW0);
    float* pEW1  = sym(d_EXW1);

    const int L1W = 256*H4;   // layer-1 offset in [L,H,4H] weights
    const int MB = BATCH*NSTMT;  // 640

    init_kernel<<<512, 256>>>();
    build_cats<<<(512*H4 + 255)/256, 256>>>(sk_Wx, sk_Wh, ex_Wx, ex_Wh);

    // statement embedder: single LSTM step from zero state (h=0 => no Wh term)
    launch_gemm(node_emb, st_Wx,        st_b,        pG0, MB, H4, HID);
    lstm_elt_first<<<MB, 256>>>(pG0, pHP1);
    launch_gemm(pHP1,     st_Wx + L1W,  st_b + H4,   pG0, MB, H4, HID);
    lstm_elt_first<<<MB, 256>>>(pG0, pSTMT);

    // xg0 = stmt @ skWx0 + skb0  (shared by all 81 starts)
    launch_gemm(pSTMT, sk_Wx, sk_b, pXG0, MB, H4, HID);

    // skip encoder: 80 steps over growing prefix of chains (s-major ordering)
    for (int idx = 0; idx < NSTMT; idx++) {
        int M = BATCH*(idx+1);
        launch_gemm(pSH0, sk_Wh, nullptr, pG0, M, H4, HID);
        skip_elt0<<<M, 256>>>(idx);
        launch_gemm(pXH1, pW1C, sk_b + H4, pG1, M, H4, 512);
        skip_elt_ln<<<M, 256>>>(idx, ln_s, ln_b);
    }

    // keys = skip @ ws + bs
    launch_gemm(pSKIP, ws, bs, pKEYS, BATCH*NNODE*NNODE, HID, HID);

    // main interpreter loop
    for (int step = 0; step < NSTEP; step++) {
        launch_gemm(pHC, wk, bk, pQ, CHAINS, HID, H4);
        attn_kernel<<<CHAINS, 256>>>(w1, b1, step);
        newp_kernel<<<BATCH, 96>>>();
        props_kernel<<<CHAINS, 256>>>();
        launch_gemm(pXHE, pEW0, ex_b,      pGE, CHAINS, H4, 512);
        exec_elt0<<<CHAINS, 256>>>();
        launch_gemm(pXH2, pEW1, ex_b + H4, pGE, CHAINS, H4, 512);
        exec_elt1<<<CHAINS, 256>>>();
    }

    out_kernel<<<(VOCAB + 255)/256, 256>>>(exit_idx, wo, bo, out);
}

// round 2
// speedup vs baseline: 1.4845x; 1.4845x over previous
#include <cuda_runtime.h>
#include <cuda_bf16.h>
#include <math.h>

// Problem constants
#define BATCH 8
#define NSTMT 80
#define NNODE 81
#define HID   256
#define H4    1024
#define NSTEP 8
#define VOCAB 30000
#define CHAINS (NNODE*BATCH)   // 648

// ---------------- device scratch (allocation-free) ----------------
static __device__ float d_SKIP[BATCH*NNODE*NNODE*HID];   // [b][start][pos][h]
static __device__ float d_KEYS[BATCH*NNODE*NNODE*HID];
static __device__ float d_STMT[BATCH*NSTMT*HID];
static __device__ float d_TMPH[BATCH*NSTMT*HID];
static __device__ float d_XG0 [BATCH*NSTMT*H4];          // stmt@skWx0 + skb0 (interleaved)
static __device__ float d_SC0[CHAINS*HID];  // c0 (LN'd between steps; raw inside a step)
static __device__ float d_SH0[CHAINS*HID];  // h0 LN'd (GEMM1 A operand)
static __device__ float d_SC1[CHAINS*HID];
static __device__ float d_SH1[CHAINS*HID];
static __device__ float d_RH0[CHAINS*HID];  // raw h0 this step
static __device__ float d_RH1[CHAINS*HID];  // raw h1 this step
static __device__ float d_XH1[CHAINS*512];  // [h0_raw_new, h1_prev_LN]
static __device__ float d_HC [CHAINS*H4];   // exec state: c0,h0,c1,h1
static __device__ float d_Q  [CHAINS*HID];
static __device__ float d_T  [BATCH*NNODE*NNODE];
static __device__ float d_P  [CHAINS];
static __device__ float d_XHE[CHAINS*512];  // [x_in, h0prop]
static __device__ float d_XH2[CHAINS*512];  // [h0new, h1prop]
static __device__ float d_CPR[CHAINS*512];  // [c0prop, c1prop]
// interleaved weights (col' = 4h + gate)
static __device__ float d_WST0[HID*H4];
static __device__ float d_WST1[HID*H4];
static __device__ float d_WSKX0[HID*H4];
static __device__ float d_WSKH0[HID*H4];
static __device__ float d_WSK1[512*H4];   // [skWx1; skWh1]
static __device__ float d_WEX0[512*H4];   // [exWx0; exWh0]
static __device__ float d_WEX1[512*H4];   // [exWx1; exWh1]
static __device__ float d_BST0[H4], d_BST1[H4], d_BSK0[H4], d_BSK1[H4], d_BEX0[H4], d_BEX1[H4];

// ---------------- helpers ----------------
__device__ __forceinline__ float sigf(float x){ return 1.f/(1.f+__expf(-x)); }
__device__ __forceinline__ float ftanh(float x){ return 1.f - 2.f/(__expf(2.f*x)+1.f); }

__device__ __forceinline__ float block_sum(float v, float* sh) {
    int lane = threadIdx.x & 31, w = threadIdx.x >> 5;
    #pragma unroll
    for (int o = 16; o; o >>= 1) v += __shfl_xor_sync(0xffffffffu, v, o);
    __syncthreads();
    if (lane == 0) sh[w] = v;
    __syncthreads();
    return sh[0]+sh[1]+sh[2]+sh[3]+sh[4]+sh[5]+sh[6]+sh[7];
}

// ---------------- init / weight prep ----------------
__global__ void init_kernel() {
    int stride = gridDim.x * blockDim.x;
    int gid = blockIdx.x * blockDim.x + threadIdx.x;
    for (int i = gid; i < BATCH*NNODE*NNODE*HID; i += stride) d_SKIP[i] = 0.f;
    for (int i = gid; i < CHAINS*HID; i += stride) {
        d_SC0[i]=0.f; d_SH0[i]=0.f; d_SC1[i]=0.f; d_SH1[i]=0.f;
    }
    for (int i = gid; i < CHAINS*512; i += stride) d_XH1[i] = 0.f;
    for (int i = gid; i < CHAINS*H4; i += stride) d_HC[i] = 0.f;
    for (int i = gid; i < CHAINS; i += stride) d_P[i] = (i % NNODE == 0) ? 1.f : 0.f;
}

__global__ void build_w(const float* __restrict__ stWx, const float* __restrict__ skWx,
                        const float* __restrict__ skWh, const float* __restrict__ exWx,
                        const float* __restrict__ exWh) {
    int i = blockIdx.x*256 + threadIdx.x;
    if (i >= 512*H4) return;
    int k = i >> 10, n = i & 1023;
    int h = n >> 2, g = n & 3;
    int sc = h + 256*g;                 // source (non-interleaved) column
    const int L1 = 256*H4;
    d_WSK1[i] = (k < 256) ? skWx[L1 + k*H4 + sc] : skWh[L1 + (k-256)*H4 + sc];
    d_WEX0[i] = (k < 256) ? exWx[k*H4 + sc]      : exWh[(k-256)*H4 + sc];
    d_WEX1[i] = (k < 256) ? exWx[L1 + k*H4 + sc] : exWh[L1 + (k-256)*H4 + sc];
    if (k < 256) {
        d_WST0[k*H4 + n]  = stWx[k*H4 + sc];
        d_WST1[k*H4 + n]  = stWx[L1 + k*H4 + sc];
        d_WSKX0[k*H4 + n] = skWx[k*H4 + sc];
        d_WSKH0[k*H4 + n] = skWh[k*H4 + sc];
    }
}

__global__ void build_b(const float* __restrict__ st_b, const float* __restrict__ sk_b,
                        const float* __restrict__ ex_b) {
    int i = blockIdx.x*256 + threadIdx.x;
    if (i >= H4) return;
    int h = i >> 2, g = i & 3;
    int sc = h + 256*g;
    d_BST0[i] = st_b[sc];       d_BST1[i] = st_b[H4 + sc];
    d_BSK0[i] = sk_b[sc];       d_BSK1[i] = sk_b[H4 + sc];
    d_BEX0[i] = ex_b[sc];       d_BEX1[i] = ex_b[H4 + sc];
}

// ---------------- fused GEMM + LSTM-cell epilogue ----------------
// C[M,N] = A[M,K] @ B[K,N]; 32x64 tile, 128 threads, 4x4/thread, double-buffered.
// EPI: 0 plain(+bias), 1 stmt-cell(zero carry), 2 skip L0, 3 skip L1, 4 exec L0, 5 exec L1
template<int EPI>
__global__ void __launch_bounds__(128) gemm_epi(
    const float* __restrict__ A, const float* __restrict__ B,
    const float* __restrict__ bias, float* __restrict__ C,
    int M, int K, int N,
    float* __restrict__ p1, float* __restrict__ p2, float* __restrict__ p3,
    const float* __restrict__ p4, int idx)
{
    __shared__ float As[2][16][36];
    __shared__ float Bs[2][16][64];
    const int tid = threadIdx.x;
    const int tx = tid & 15, ty = tid >> 4;
    const int row0 = blockIdx.y * 32;
    const int col0 = blockIdx.x * 64;
    const int T = K >> 4;
    const int am = tid >> 2;
    const int ak = (tid & 3) << 2;
    const int bk = tid >> 4;          // 0..7
    const int bn = (tid & 15) << 2;
    const int gmA = row0 + am;
    float acc[4][4] = {};
    float4 ra, rb0, rb1;
    // prologue: tile 0
    ra = (gmA < M) ? *(const float4*)&A[gmA*K + ak] : make_float4(0.f,0.f,0.f,0.f);
    rb0 = *(const float4*)&B[bk*N + col0 + bn];
    rb1 = *(const float4*)&B[(bk+8)*N + col0 + bn];
    As[0][ak][am]=ra.x; As[0][ak+1][am]=ra.y; As[0][ak+2][am]=ra.z; As[0][ak+3][am]=ra.w;
    *(float4*)&Bs[0][bk][bn] = rb0;
    *(float4*)&Bs[0][bk+8][bn] = rb1;
    __syncthreads();
    for (int t = 0; t < T; t++) {
        const int p = t & 1;
        if (t+1 < T) {
            int k0 = (t+1) << 4;
            ra = (gmA < M) ? *(const float4*)&A[gmA*K + k0 + ak] : make_float4(0.f,0.f,0.f,0.f);
            rb0 = *(const float4*)&B[(k0+bk)*N + col0 + bn];
            rb1 = *(const float4*)&B[(k0+bk+8)*N + col0 + bn];
        }
        #pragma unroll
        for (int kk = 0; kk < 16; kk++) {
            float4 b4 = *(const float4*)&Bs[p][kk][tx<<2];
            float4 a4 = *(const float4*)&As[p][kk][ty<<2];
            acc[0][0]+=a4.x*b4.x; acc[0][1]+=a4.x*b4.y; acc[0][2]+=a4.x*b4.z; acc[0][3]+=a4.x*b4.w;
            acc[1][0]+=a4.y*b4.x; acc[1][1]+=a4.y*b4.y; acc[1][2]+=a4.y*b4.z; acc[1][3]+=a4.y*b4.w;
            acc[2][0]+=a4.z*b4.x; acc[2][1]+=a4.z*b4.y; acc[2][2]+=a4.z*b4.z; acc[2][3]+=a4.z*b4.w;
            acc[3][0]+=a4.w*b4.x; acc[3][1]+=a4.w*b4.y; acc[3][2]+=a4.w*b4.z; acc[3][3]+=a4.w*b4.w;
        }
        if (t+1 < T) {
            const int q = p ^ 1;
            As[q][ak][am]=ra.x; As[q][ak+1][am]=ra.y; As[q][ak+2][am]=ra.z; As[q][ak+3][am]=ra.w;
            *(float4*)&Bs[q][bk][bn] = rb0;
            *(float4*)&Bs[q][bk+8][bn] = rb1;
            __syncthreads();
        }
    }

    if (EPI == 0) {
        float4 bv = make_float4(0.f,0.f,0.f,0.f);
        if (bias) bv = *(const float4*)&bias[col0 + (tx<<2)];
        #pragma unroll
        for (int i = 0; i < 4; i++) {
            int gm = row0 + (ty<<2) + i;
            if (gm >= M) continue;
            float4 v = make_float4(acc[i][0]+bv.x, acc[i][1]+bv.y, acc[i][2]+bv.z, acc[i][3]+bv.w);
            *(float4*)&C[gm*N + col0 + (tx<<2)] = v;
        }
    } else {
        const int h = (col0 >> 2) + tx;          // hidden unit index
        float4 bv = make_float4(0.f,0.f,0.f,0.f);
        if (bias) bv = *(const float4*)&bias[h<<2];
        #pragma unroll
        for (int i = 0; i < 4; i++) {
            int gm = row0 + (ty<<2) + i;
            if (gm >= M) continue;
            float gi = acc[i][0]+bv.x, gf = acc[i][1]+bv.y, gg = acc[i][2]+bv.z, go = acc[i][3]+bv.w;
            if (EPI == 2) {
                const float4 xv = *(const float4*)&p4[(((gm&7)*NSTMT)+idx)*H4 + (h<<2)];
                gi+=xv.x; gf+=xv.y; gg+=xv.z; go+=xv.w;
            }
            if (EPI == 1) {
                float cv = sigf(gi)*ftanh(gg);
                p1[gm*HID + h] = sigf(go)*ftanh(cv);
            } else if (EPI == 2) {
                float cp = p1[gm*HID + h];
                float cv = sigf(gf)*cp + sigf(gi)*ftanh(gg);
                float hv = sigf(go)*ftanh(cv);
                p1[gm*HID + h] = cv;          // raw c0
                p2[gm*HID + h] = hv;          // raw h0
                p3[gm*512 + h] = hv;          // XH1 first half
            } else if (EPI == 3) {
                float cp = p1[gm*HID + h];
                float cv = sigf(gf)*cp + sigf(gi)*ftanh(gg);
                float hv = sigf(go)*ftanh(cv);
                p1[gm*HID + h] = cv;          // raw c1
                p2[gm*HID + h] = hv;          // raw h1
                int s = gm >> 3, b = gm & 7;
                p3[((b*NNODE + s)*NNODE + (idx+1))*HID + h] = hv;   // skip output (pre-LN h1)
            } else if (EPI == 4) {
                float cp = p1[gm*512 + h];    // c0 prop
                float cv = sigf(gf)*cp + sigf(gi)*ftanh(gg);
                float hv = sigf(go)*ftanh(cv);
                p2[gm*H4 + h]       = cv;     // HC c0
                p2[gm*H4 + HID + h] = hv;     // HC h0
                p3[gm*512 + h]      = hv;     // XH2 first half
            } else {
                float cp = p1[gm*512 + HID + h];  // c1 prop
                float cv = sigf(gf)*cp + sigf(gi)*ftanh(gg);
                float hv = sigf(go)*ftanh(cv);
                p2[gm*H4 + 512 + h] = cv;     // HC c1
                p2[gm*H4 + 768 + h] = hv;     // HC h1
            }
        }
    }
}

// ---------------- LayerNorm over concat(c0,h0,c1,h1), writes next-step operands ----------------
__global__ void __launch_bounds__(256) ln_kernel(const float* __restrict__ lns,
                                                 const float* __restrict__ lnb) {
    __shared__ float sh[8];
    int c = blockIdx.x, j = threadIdx.x;
    float v0 = d_SC0[c*HID+j];   // raw c0
    float v1 = d_RH0[c*HID+j];   // raw h0
    float v2 = d_SC1[c*HID+j];   // raw c1
    float v3 = d_RH1[c*HID+j];   // raw h1
    float mu = block_sum(v0+v1+v2+v3, sh) * (1.f/1024.f);
    float e0 = v0-mu, e1 = v1-mu, e2 = v2-mu, e3 = v3-mu;
    float var = block_sum(e0*e0+e1*e1+e2*e2+e3*e3, sh) * (1.f/1024.f);
    float rs = rsqrtf(var + 1e-6f);
    d_SC0[c*HID+j] = e0*rs*lns[j]       + lnb[j];
    d_SH0[c*HID+j] = e1*rs*lns[256+j]   + lnb[256+j];
    d_SC1[c*HID+j] = e2*rs*lns[512+j]   + lnb[512+j];
    float h1 =        e3*rs*lns[768+j]  + lnb[768+j];
    d_SH1[c*HID+j] = h1;
    d_XH1[c*512 + 256 + j] = h1;
}

// ---------------- main-loop kernels ----------------
__global__ void __launch_bounds__(256) attn_kernel(const float* __restrict__ w1,
                                                   const float* __restrict__ b1, int step) {
    int bn = blockIdx.x;               // b*81 + n
    int n = bn % NNODE;
    __shared__ float qsh[HID], w1sh[HID], lg[NNODE];
    int tid = threadIdx.x;
    qsh[tid]  = d_Q[bn*HID + tid];
    w1sh[tid] = w1[tid];
    __syncthreads();
    int w = tid >> 5, lane = tid & 31;
    float b1v = b1[0];
    for (int m = w; m < NNODE; m += 8) {
        const float* kr = d_KEYS + (bn*NNODE + m)*HID;
        float acc = 0.f;
        #pragma unroll 4
        for (int h = lane; h < HID; h += 32)
            acc += ftanh(qsh[h] + kr[h]) * w1sh[h];
        #pragma unroll
        for (int o = 16; o; o >>= 1) acc += __shfl_xor_sync(0xffffffffu, acc, o);
        if (lane == 0) {
            bool allowed = (step == 0) ? (m == 1)
                        : ((step == NSTEP-1) ? (m == NNODE-1)
                                             : (m > n || m == NNODE-1));
            lg[m] = allowed ? (acc + b1v) : -1e9f;
        }
    }
    __syncthreads();
    if (w == 0) {
        float mx = -1e30f;
        for (int m = lane; m < NNODE; m += 32) mx = fmaxf(mx, lg[m]);
        #pragma unroll
        for (int o = 16; o; o >>= 1) mx = fmaxf(mx, __shfl_xor_sync(0xffffffffu, mx, o));
        float sum = 0.f;
        for (int m = lane; m < NNODE; m += 32) { float e = expf(lg[m]-mx); lg[m] = e; sum += e; }
        #pragma unroll
        for (int o = 16; o; o >>= 1) sum += __shfl_xor_sync(0xffffffffu, sum, o);
        float scale = d_P[bn] / sum;
        for (int m = lane; m < NNODE; m += 32) d_T[bn*NNODE + m] = lg[m]*scale;
    }
}

__global__ void newp_kernel() {
    int b = blockIdx.x, m = threadIdx.x;
    if (m < NNODE) {
        float s = 0.f;
        for (int n = 0; n < NNODE; n++) s += d_T[(b*NNODE+n)*NNODE + m];
        d_P[b*NNODE + m] = s;
    }
}

__global__ void __launch_bounds__(256) props_kernel() {
    int bm = blockIdx.x;
    int b = bm / NNODE, m = bm % NNODE;
    __shared__ float tsh[NNODE];
    int tid = threadIdx.x;
    if (tid < NNODE) tsh[tid] = d_T[(b*NNODE+tid)*NNODE + m];
    __syncthreads();
    float inv = 1.f / (d_P[bm] + 1e-7f);
    float ax=0.f, a0=0.f, a1=0.f, a2=0.f, a3=0.f;
    for (int n = 0; n < NNODE; n++) {
        float tv = tsh[n];
        if (tv == 0.f) continue;
        const float* sr = d_SKIP + ((b*NNODE+n)*NNODE + m)*HID;
        const float* hr = d_HC + (b*NNODE+n)*H4;
        ax += tv*sr[tid];
        a0 += tv*hr[tid];      a1 += tv*hr[256+tid];
        a2 += tv*hr[512+tid];  a3 += tv*hr[768+tid];
    }
    d_XHE[bm*512 + tid]       = ax*inv;  // x_in
    d_CPR[bm*512 + tid]       = a0*inv;  // c0 prop
    d_XHE[bm*512 + 256 + tid] = a1*inv;  // h0 prop
    d_CPR[bm*512 + 256 + tid] = a2*inv;  // c1 prop
    d_XH2[bm*512 + 256 + tid] = a3*inv;  // h1 prop
}

// ---------------- output projection ----------------
__global__ void __launch_bounds__(256) out_kernel(const int* __restrict__ exit_idx,
                                                  const float* __restrict__ wo,
                                                  const float* __restrict__ bo,
                                                  float* __restrict__ out) {
    __shared__ float hex[BATCH][HID];
    int tid = threadIdx.x;
    for (int i = tid; i < BATCH*HID; i += 256) {
        int b = i >> 8, h = i & 255;
        hex[b][h] = d_HC[(b*NNODE + exit_idx[b])*H4 + 768 + h];
    }
    __syncthreads();
    int col = blockIdx.x*256 + tid;
    if (col >= VOCAB) return;
    float acc[BATCH];
    #pragma unroll
    for (int b = 0; b < BATCH; b++) acc[b] = 0.f;
    for (int h = 0; h < HID; h++) {
        float wv = wo[h*VOCAB + col];
        #pragma unroll
        for (int b = 0; b < BATCH; b++) acc[b] += hex[b][h]*wv;
    }
    float bv = bo[col];
    #pragma unroll
    for (int b = 0; b < BATCH; b++) out[b*VOCAB + col] = acc[b] + bv;
}

// ---------------- host ----------------
static inline float* sym(const void* s) {
    void* p = nullptr;
    cudaGetSymbolAddress(&p, s);
    return (float*)p;
}

template<int EPI>
static inline void launch_gemm(const float* A, const float* B, const float* bias, float* C,
                               int M, int K, int N,
                               float* p1 = 0, float* p2 = 0, float* p3 = 0,
                               const float* p4 = 0, int idx = 0) {
    dim3 g(N/64, (M+31)/32);
    gemm_epi<EPI><<<g, 128>>>(A, B, bias, C, M, K, N, p1, p2, p3, p4, idx);
}

extern "C" void kernel_launch(void* const* d_in, const int* in_sizes, int n_in,
                              void* d_out, int out_size) {
    const float* node_emb = (const float*)d_in[0];
    const int*   exit_idx = (const int*)  d_in[10];
    const float* st_Wx = (const float*)d_in[12];
    const float* st_b  = (const float*)d_in[14];
    const float* sk_Wx = (const float*)d_in[15];
    const float* sk_Wh = (const float*)d_in[16];
    const float* sk_b  = (const float*)d_in[17];
    const float* ln_s  = (const float*)d_in[18];
    const float* ln_b  = (const float*)d_in[19];
    const float* ex_Wx = (const float*)d_in[20];
    const float* ex_Wh = (const float*)d_in[21];
    const float* ex_b  = (const float*)d_in[22];
    const float* wk = (const float*)d_in[23];
    const float* bk = (const float*)d_in[24];
    const float* ws = (const float*)d_in[25];
    const float* bs = (const float*)d_in[26];
    const float* w1 = (const float*)d_in[27];
    const float* b1 = (const float*)d_in[28];
    const float* wo = (const float*)d_in[29];
    const float* bo = (const float*)d_in[30];
    float* out = (float*)d_out;

    float* pSTMT = sym(d_STMT);
    float* pTMPH = sym(d_TMPH);
    float* pXG0  = sym(d_XG0);
    float* pSKIP = sym(d_SKIP);
    float* pKEYS = sym(d_KEYS);
    float* pSC0  = sym(d_SC0);
    float* pSH0  = sym(d_SH0);
    float* pSC1  = sym(d_SC1);
    float* pRH0  = sym(d_RH0);
    float* pRH1  = sym(d_RH1);
    float* pXH1  = sym(d_XH1);
    float* pHC   = sym(d_HC);
    float* pQ    = sym(d_Q);
    float* pXHE  = sym(d_XHE);
    float* pXH2  = sym(d_XH2);
    float* pCPR  = sym(d_CPR);
    float* pWST0 = sym(d_WST0);
    float* pWST1 = sym(d_WST1);
    float* pWSKX0= sym(d_WSKX0);
    float* pWSKH0= sym(d_WSKH0);
    float* pWSK1 = sym(d_WSK1);
    float* pWEX0 = sym(d_WEX0);
    float* pWEX1 = sym(d_WEX1);
    float* pBST0 = sym(d_BST0);
    float* pBST1 = sym(d_BST1);
    float* pBSK0 = sym(d_BSK0);
    float* pBSK1 = sym(d_BSK1);
    float* pBEX0 = sym(d_BEX0);
    float* pBEX1 = sym(d_BEX1);

    const int MB = BATCH*NSTMT;  // 640

    init_kernel<<<512, 256>>>();
    build_w<<<(512*H4 + 255)/256, 256>>>(st_Wx, sk_Wx, sk_Wh, ex_Wx, ex_Wh);
    build_b<<<(H4 + 255)/256, 256>>>(st_b, sk_b, ex_b);

    // statement embedder: single LSTM step from zero state (h=0 => no Wh term)
    launch_gemm<1>(node_emb, pWST0, pBST0, nullptr, MB, HID, H4, pTMPH);
    launch_gemm<1>(pTMPH,    pWST1, pBST1, nullptr, MB, HID, H4, pSTMT);

    // xg0 = stmt @ skWx0 + skb0 (interleaved), shared by all 81 starts
    launch_gemm<0>(pSTMT, pWSKX0, pBSK0, pXG0, MB, HID, H4);

    // skip encoder: 80 steps over growing prefix of chains (s-major ordering)
    for (int idx = 0; idx < NSTMT; idx++) {
        int M = BATCH*(idx+1);
        launch_gemm<2>(pSH0, pWSKH0, nullptr, nullptr, M, HID, H4,
                       pSC0, pRH0, pXH1, pXG0, idx);
        launch_gemm<3>(pXH1, pWSK1, pBSK1, nullptr, M, 512, H4,
                       pSC1, pRH1, pSKIP, nullptr, idx);
        ln_kernel<<<M, 256>>>(ln_s, ln_b);
    }

    // keys = skip @ ws + bs
    launch_gemm<0>(pSKIP, ws, bs, pKEYS, BATCH*NNODE*NNODE, HID, HID);

    // main interpreter loop
    for (int step = 0; step < NSTEP; step++) {
        launch_gemm<0>(pHC, wk, bk, pQ, CHAINS, H4, HID);
        attn_kernel<<<CHAINS, 256>>>(w1, b1, step);
        newp_kernel<<<BATCH, 96>>>();
        props_kernel<<<CHAINS, 256>>>();
        launch_gemm<4>(pXHE, pWEX0, pBEX0, nullptr, CHAINS, 512, H4,
                       pCPR, pHC, pXH2);
        launch_gemm<5>(pXH2, pWEX1, pBEX1, nullptr, CHAINS, 512, H4,
                       pCPR, pHC, nullptr);
    }

    out_kernel<<<(VOCAB + 255)/256, 256>>>(exit_idx, wo, bo, out);
}